// round 9
// baseline (speedup 1.0000x reference)
#include <cuda_runtime.h>
#include <cuda_bf16.h>
#include <cuda_fp16.h>
#include <cstdint>
#include <math.h>

// ============================================================================
// MLP: out[e] = gelu_tanh(x[e] @ w1[e]) @ w2[e]
//   E=8, T=2048, H=1024, F=4096, fp32 in/out.
// Both GEMMs: 2-product fp16 split (A fp16 single, B fp16 hi/lo), fp32 acc.
// warp mma.sync m16n8k16; 8 warps, warp tile 64x32, CTA 128x128.
// R9: CTA_K=32, 64B rows + SW64 swizzle (x ^ ((x>>3)&0x30)), 4 stages x 24KB
//     = 96KB smem, 2 CTAs/SM, single __syncthreads per iter, lookahead 3.
// Error (calibrated): 2.08e-4 per fp16 rounding event x2 -> ~3e-4 (thr 1e-3).
// ============================================================================

static constexpr int E_ = 8, T_ = 2048, H_ = 1024, F_ = 4096;

// -------- static device scratch --------
__device__ __half g_x16[(size_t)E_ * T_ * H_];        // x fp16
__device__ __half g_w1h[(size_t)E_ * F_ * H_];        // w1^T: [E,F,H] fp16 hi
__device__ __half g_w1l[(size_t)E_ * F_ * H_];
__device__ __half g_w2h[(size_t)E_ * H_ * F_];        // w2^T: [E,H,F] fp16 hi
__device__ __half g_w2l[(size_t)E_ * H_ * F_];
__device__ __half g_h16[(size_t)E_ * T_ * F_];        // gelu(x@w1) fp16

// -------- helpers --------
__device__ __forceinline__ uint32_t smem_u32(const void* p) {
    return (uint32_t)__cvta_generic_to_shared(p);
}
__device__ __forceinline__ void cp16(uint32_t s, const void* g) {
    asm volatile("cp.async.cg.shared.global [%0], [%1], 16;\n"
                 :: "r"(s), "l"(__cvta_generic_to_global(g)));
}
__device__ __forceinline__ void cp_commit() {
    asm volatile("cp.async.commit_group;\n" ::: "memory");
}
template <int N> __device__ __forceinline__ void cp_wait() {
    asm volatile("cp.async.wait_group %0;\n" :: "n"(N) : "memory");
}
// 64B-row swizzle: XOR row bits [8:7] into 16B-chunk bits [5:4].
// Verified: 8-row LDSM phases -> bank groups {0,4,1,5,2,6,3,7}, conflict-free.
#define SWZ64(x) ((x) ^ (((x) >> 3) & 0x30))

#define LDSM_X4(r0, r1, r2, r3, a)                                          \
    asm volatile("ldmatrix.sync.aligned.m8n8.x4.shared.b16 {%0,%1,%2,%3}, [%4];" \
                 : "=r"(r0), "=r"(r1), "=r"(r2), "=r"(r3) : "r"(a))

__device__ __forceinline__ void mma16816(float* c, const uint32_t* a, const uint32_t* b) {
    asm volatile(
        "mma.sync.aligned.m16n8k16.row.col.f32.f16.f16.f32 "
        "{%0,%1,%2,%3}, {%4,%5,%6,%7}, {%8,%9}, {%0,%1,%2,%3};\n"
        : "+f"(c[0]), "+f"(c[1]), "+f"(c[2]), "+f"(c[3])
        : "r"(a[0]), "r"(a[1]), "r"(a[2]), "r"(a[3]), "r"(b[0]), "r"(b[1]));
}

__device__ __forceinline__ float gelu_tanh_f(float x) {
    float inner = 0.7978845608028654f * (x + 0.044715f * x * x * x);
    return 0.5f * x * (1.0f + tanhf(inner));
}

// -------- pre-pass: fp32 -> fp16 convert (x) --------
__global__ void conv16_k(const float* __restrict__ in, __half* __restrict__ o, size_t n4) {
    size_t i = (size_t)blockIdx.x * blockDim.x + threadIdx.x;
    if (i >= n4) return;
    float4 v = ((const float4*)in)[i];
    __half2 a = __floats2half2_rn(v.x, v.y);
    __half2 b = __floats2half2_rn(v.z, v.w);
    ((uint2*)o)[i] = make_uint2(*(uint32_t*)&a, *(uint32_t*)&b);
}

// -------- pre-pass: transpose [E,R,C] -> [E,C,R] + fp16 hi/lo split --------
// 4 consecutive rows per thread -> 64-bit stores.
__global__ void tsplit16(const float* __restrict__ in, __half* __restrict__ hi,
                         __half* __restrict__ lo, int R, int C) {
    __shared__ float t[32][33];  // t[r_local][c_local]
    int e = blockIdx.z;
    const float* ip = in + (size_t)e * R * C;
    size_t ob = (size_t)e * R * C;
    int c0 = blockIdx.x * 32, r0 = blockIdx.y * 32;
    int tx = threadIdx.x, ty = threadIdx.y;
    for (int j = ty; j < 32; j += 8)
        t[j][tx] = ip[(size_t)(r0 + j) * C + c0 + tx];
    __syncthreads();
    int idx = ty * 32 + tx;          // 0..255
    int cc = idx >> 3;               // 0..31
    int rr = (idx & 7) * 4;          // 0,4,..,28
    __half h[4], l[4];
#pragma unroll
    for (int j = 0; j < 4; j++) {
        float v = t[rr + j][cc];
        h[j] = __float2half_rn(v);
        l[j] = __float2half_rn(v - __half2float(h[j]));
    }
    size_t o = ob + (size_t)(c0 + cc) * R + r0 + rr;
    __half2 hp0 = __halves2half2(h[0], h[1]), hp1 = __halves2half2(h[2], h[3]);
    __half2 lp0 = __halves2half2(l[0], l[1]), lp1 = __halves2half2(l[2], l[3]);
    *(uint2*)(hi + o) = make_uint2(*(uint32_t*)&hp0, *(uint32_t*)&hp1);
    *(uint2*)(lo + o) = make_uint2(*(uint32_t*)&lp0, *(uint32_t*)&lp1);
}

// -------- warp-mma GEMM: C[M,N] = A[M,K] @ B[N,K]^T, 2 fp16 products ------
#define CTA_M 128
#define CTA_N 128
#define CTA_K 32
#define NTHREADS 256
#define ARR_BYTES (128 * 64)        // 128 rows x 64B (32 halves) = 8 KB
#define STAGE_BYTES (3 * ARR_BYTES) // A, Bh, Bl = 24 KB
#define NSTAGES 4
#define SMEM_TOTAL (NSTAGES * STAGE_BYTES)  // 96 KB -> 2 CTAs/SM

template <bool FUSE_GELU>
__global__ __launch_bounds__(NTHREADS, 2)
void gemm_wm(const __half* __restrict__ A0, const __half* __restrict__ B0,
             const __half* __restrict__ B1, float* __restrict__ Cf,
             __half* __restrict__ Ch, int M, int N, int K) {
    extern __shared__ __align__(1024) char smem[];
    uint32_t sb = smem_u32(smem);
    const int tid = threadIdx.x, warp = tid >> 5, lid = tid & 31;
    const int e = blockIdx.z;
    const int m0 = blockIdx.y * CTA_M, n0 = blockIdx.x * CTA_N;
    const int wm = (warp >> 2) * 64;    // 2 warp rows x 64
    const int wn = (warp & 3) * 32;     // 4 warp cols x 32
    const int g = lid >> 2, q = lid & 3;

    size_t eA = (size_t)e * M * K, eB = (size_t)e * N * K;
    const __half* gA = A0 + eA + (size_t)m0 * K;
    const __half* gBh = B0 + eB + (size_t)n0 * K;
    const __half* gBl = B1 + eB + (size_t)n0 * K;

    float acc[4][4][4];
#pragma unroll
    for (int mi = 0; mi < 4; mi++)
#pragma unroll
        for (int ni = 0; ni < 4; ni++)
#pragma unroll
            for (int k2 = 0; k2 < 4; k2++) acc[mi][ni][k2] = 0.0f;

    // stage load: per array 512 16B-chunks; chunk c: row=c>>2, h=c&3
    auto load_stage = [&](int kt, int s) {
        uint32_t st = sb + s * STAGE_BYTES;
        int k0 = kt * CTA_K;
#pragma unroll
        for (int i = 0; i < 2; i++) {
            int c = i * NTHREADS + tid;
            int row = c >> 2, h = c & 3;
            uint32_t rel = (uint32_t)(row * 64 + h * 16);
            uint32_t sw = SWZ64(rel);
            size_t go = (size_t)row * K + k0 + h * 8;
            cp16(st + sw, gA + go);
            cp16(st + ARR_BYTES + sw, gBh + go);
            cp16(st + 2 * ARR_BYTES + sw, gBl + go);
        }
    };

    auto compute = [&](int s) {
        uint32_t st = sb + s * STAGE_BYTES;
        uint32_t aA = st;
        uint32_t bH = st + ARR_BYTES, bL = st + 2 * ARR_BYTES;
#pragma unroll
        for (int kk = 0; kk < CTA_K; kk += 16) {
            uint32_t av[4][4], bb[4][2];
            // A fragments: 4 x LDSM.x4 (64 rows x 16 k)
            {
                int arow = wm + (lid & 15);
                uint32_t acol = (uint32_t)(kk * 2 + (lid >> 4) * 16);
#pragma unroll
                for (int mi = 0; mi < 4; mi++) {
                    uint32_t rel = (uint32_t)((arow + mi * 16) * 64) + acol;
                    uint32_t ad = SWZ64(rel);
                    LDSM_X4(av[mi][0], av[mi][1], av[mi][2], av[mi][3], aA + ad);
                }
            }
            int brow = wn + ((lid >> 4) & 1) * 8 + (lid & 7);
            uint32_t bcol = (uint32_t)(kk * 2 + ((lid >> 3) & 1) * 16);
            // Bh fragments (2 x LDSM.x4) + 16 MMAs
#pragma unroll
            for (int nf = 0; nf < 2; nf++) {
                uint32_t rel = (uint32_t)((brow + nf * 16) * 64) + bcol;
                uint32_t ad = SWZ64(rel);
                LDSM_X4(bb[nf * 2][0], bb[nf * 2][1], bb[nf * 2 + 1][0], bb[nf * 2 + 1][1],
                        bH + ad);
            }
#pragma unroll
            for (int mi = 0; mi < 4; mi++)
#pragma unroll
                for (int ni = 0; ni < 4; ni++) mma16816(acc[mi][ni], av[mi], bb[ni]);
            // Bl fragments (reuse regs) + 16 MMAs
#pragma unroll
            for (int nf = 0; nf < 2; nf++) {
                uint32_t rel = (uint32_t)((brow + nf * 16) * 64) + bcol;
                uint32_t ad = SWZ64(rel);
                LDSM_X4(bb[nf * 2][0], bb[nf * 2][1], bb[nf * 2 + 1][0], bb[nf * 2 + 1][1],
                        bL + ad);
            }
#pragma unroll
            for (int mi = 0; mi < 4; mi++)
#pragma unroll
                for (int ni = 0; ni < 4; ni++) mma16816(acc[mi][ni], av[mi], bb[ni]);
        }
    };

    const int NK = K / CTA_K;
    load_stage(0, 0);
    cp_commit();
    load_stage(1, 1);
    cp_commit();
    load_stage(2, 2);
    cp_commit();

    for (int kt = 0; kt < NK; kt++) {
        cp_wait<2>();           // stage kt loads complete (2 younger groups pending)
        __syncthreads();        // data visible; stage (kt+3)&3 free (compute(kt-1) done)
        if (kt + 3 < NK) load_stage(kt + 3, (kt + 3) & 3);
        cp_commit();            // commit every iter (possibly empty) to keep count
        compute(kt & 3);
    }

    // ---- epilogue ----
#pragma unroll
    for (int mi = 0; mi < 4; mi++) {
#pragma unroll
        for (int ni = 0; ni < 4; ni++) {
            int r = m0 + wm + mi * 16 + g;
            int col = n0 + wn + ni * 8 + q * 2;
            size_t o0 = ((size_t)e * M + r) * N + col;
            size_t o1 = o0 + (size_t)8 * N;
            float v0 = acc[mi][ni][0], v1 = acc[mi][ni][1];
            float v2 = acc[mi][ni][2], v3 = acc[mi][ni][3];
            if (FUSE_GELU) {
                v0 = gelu_tanh_f(v0); v1 = gelu_tanh_f(v1);
                v2 = gelu_tanh_f(v2); v3 = gelu_tanh_f(v3);
                __half2 p0 = __floats2half2_rn(v0, v1);
                __half2 p1 = __floats2half2_rn(v2, v3);
                *(__half2*)(Ch + o0) = p0;
                *(__half2*)(Ch + o1) = p1;
            } else {
                *(float2*)(Cf + o0) = make_float2(v0, v1);
                *(float2*)(Cf + o1) = make_float2(v2, v3);
            }
        }
    }
}

// -------- host launch --------
extern "C" void kernel_launch(void* const* d_in, const int* in_sizes, int n_in,
                              void* d_out, int out_size) {
    const float* x = (const float*)d_in[0];
    const float* w1 = (const float*)d_in[1];
    const float* w2 = (const float*)d_in[2];
    float* out = (float*)d_out;

    __half *x16, *w1h, *w1l, *w2h, *w2l, *h16;
    cudaGetSymbolAddress((void**)&x16, g_x16);
    cudaGetSymbolAddress((void**)&w1h, g_w1h);
    cudaGetSymbolAddress((void**)&w1l, g_w1l);
    cudaGetSymbolAddress((void**)&w2h, g_w2h);
    cudaGetSymbolAddress((void**)&w2l, g_w2l);
    cudaGetSymbolAddress((void**)&h16, g_h16);

    cudaFuncSetAttribute(gemm_wm<true>, cudaFuncAttributeMaxDynamicSharedMemorySize, SMEM_TOTAL);
    cudaFuncSetAttribute(gemm_wm<false>, cudaFuncAttributeMaxDynamicSharedMemorySize, SMEM_TOTAL);

    // pre-pass
    size_t nx4 = (size_t)E_ * T_ * H_ / 4;
    conv16_k<<<(unsigned)((nx4 + 255) / 256), 256>>>(x, x16, nx4);
    tsplit16<<<dim3(F_ / 32, H_ / 32, E_), dim3(32, 8)>>>(w1, w1h, w1l, H_, F_);
    tsplit16<<<dim3(H_ / 32, F_ / 32, E_), dim3(32, 8)>>>(w2, w2h, w2l, F_, H_);

    // GEMM1 + GELU: A=x fp16 [T,H], B=w1^T fp16 hi/lo [F,H] -> h fp16 [T,F]
    gemm_wm<true><<<dim3(F_ / CTA_N, T_ / CTA_M, E_), NTHREADS, SMEM_TOTAL>>>(
        x16, w1h, w1l, nullptr, h16, T_, F_, H_);
    // GEMM2: A=h fp16 [T,F], B=w2^T fp16 hi/lo [H,F] -> out fp32 [T,H]
    gemm_wm<false><<<dim3(H_ / CTA_N, T_ / CTA_M, E_), NTHREADS, SMEM_TOTAL>>>(
        h16, w2h, w2l, out, nullptr, T_, H_, F_);
}

// round 10
// speedup vs baseline: 1.0115x; 1.0115x over previous
#include <cuda_runtime.h>
#include <cuda_bf16.h>
#include <cuda_fp16.h>
#include <cstdint>
#include <math.h>

// ============================================================================
// MLP: out[e] = gelu_tanh(x[e] @ w1[e]) @ w2[e]
//   E=8, T=2048, H=1024, F=4096, fp32 in/out.
// Both GEMMs: 2-product fp16 split (A fp16 single, B fp16 hi/lo), fp32 acc.
// warp mma.sync m16n8k16; 8 warps, warp tile 64x32, CTA 128x128x64,
// 2 stages x 48KB smem, 2 CTAs/SM (R8 base).
// R10: fragment double-buffering — prefetch next-kk A/Bh fragments before
//   current kk's 32 MMAs, hiding LDSM latency inside the MMA stream
//   (short-scoreboard stalls were the residual ~28% tensor-idle).
// Error (calibrated): 2.08e-4 per fp16 rounding event x2 -> ~3e-4 (thr 1e-3).
// ============================================================================

static constexpr int E_ = 8, T_ = 2048, H_ = 1024, F_ = 4096;

// -------- static device scratch --------
__device__ __half g_x16[(size_t)E_ * T_ * H_];        // x fp16
__device__ __half g_w1h[(size_t)E_ * F_ * H_];        // w1^T: [E,F,H] fp16 hi
__device__ __half g_w1l[(size_t)E_ * F_ * H_];
__device__ __half g_w2h[(size_t)E_ * H_ * F_];        // w2^T: [E,H,F] fp16 hi
__device__ __half g_w2l[(size_t)E_ * H_ * F_];
__device__ __half g_h16[(size_t)E_ * T_ * F_];        // gelu(x@w1) fp16

// -------- helpers --------
__device__ __forceinline__ uint32_t smem_u32(const void* p) {
    return (uint32_t)__cvta_generic_to_shared(p);
}
__device__ __forceinline__ void cp16(uint32_t s, const void* g) {
    asm volatile("cp.async.cg.shared.global [%0], [%1], 16;\n"
                 :: "r"(s), "l"(__cvta_generic_to_global(g)));
}
__device__ __forceinline__ void cp_commit() {
    asm volatile("cp.async.commit_group;\n" ::: "memory");
}
template <int N> __device__ __forceinline__ void cp_wait() {
    asm volatile("cp.async.wait_group %0;\n" :: "n"(N) : "memory");
}
#define SWZ(x) ((x) ^ (((x) >> 3) & 0x70))

#define LDSM_X4(r0, r1, r2, r3, a)                                          \
    asm volatile("ldmatrix.sync.aligned.m8n8.x4.shared.b16 {%0,%1,%2,%3}, [%4];" \
                 : "=r"(r0), "=r"(r1), "=r"(r2), "=r"(r3) : "r"(a))

__device__ __forceinline__ void mma16816(float* c, const uint32_t* a, const uint32_t* b) {
    asm volatile(
        "mma.sync.aligned.m16n8k16.row.col.f32.f16.f16.f32 "
        "{%0,%1,%2,%3}, {%4,%5,%6,%7}, {%8,%9}, {%0,%1,%2,%3};\n"
        : "+f"(c[0]), "+f"(c[1]), "+f"(c[2]), "+f"(c[3])
        : "r"(a[0]), "r"(a[1]), "r"(a[2]), "r"(a[3]), "r"(b[0]), "r"(b[1]));
}

__device__ __forceinline__ float gelu_tanh_f(float x) {
    float inner = 0.7978845608028654f * (x + 0.044715f * x * x * x);
    return 0.5f * x * (1.0f + tanhf(inner));
}

// -------- pre-pass: fp32 -> fp16 convert (x) --------
__global__ void conv16_k(const float* __restrict__ in, __half* __restrict__ o, size_t n4) {
    size_t i = (size_t)blockIdx.x * blockDim.x + threadIdx.x;
    if (i >= n4) return;
    float4 v = ((const float4*)in)[i];
    __half2 a = __floats2half2_rn(v.x, v.y);
    __half2 b = __floats2half2_rn(v.z, v.w);
    ((uint2*)o)[i] = make_uint2(*(uint32_t*)&a, *(uint32_t*)&b);
}

// -------- pre-pass: transpose [E,R,C] -> [E,C,R] + fp16 hi/lo split --------
__global__ void tsplit16(const float* __restrict__ in, __half* __restrict__ hi,
                         __half* __restrict__ lo, int R, int C) {
    __shared__ float t[32][33];  // t[r_local][c_local]
    int e = blockIdx.z;
    const float* ip = in + (size_t)e * R * C;
    size_t ob = (size_t)e * R * C;
    int c0 = blockIdx.x * 32, r0 = blockIdx.y * 32;
    int tx = threadIdx.x, ty = threadIdx.y;
    for (int j = ty; j < 32; j += 8)
        t[j][tx] = ip[(size_t)(r0 + j) * C + c0 + tx];
    __syncthreads();
    int idx = ty * 32 + tx;          // 0..255
    int cc = idx >> 3;               // 0..31
    int rr = (idx & 7) * 4;          // 0,4,..,28
    __half h[4], l[4];
#pragma unroll
    for (int j = 0; j < 4; j++) {
        float v = t[rr + j][cc];
        h[j] = __float2half_rn(v);
        l[j] = __float2half_rn(v - __half2float(h[j]));
    }
    size_t o = ob + (size_t)(c0 + cc) * R + r0 + rr;
    __half2 hp0 = __halves2half2(h[0], h[1]), hp1 = __halves2half2(h[2], h[3]);
    __half2 lp0 = __halves2half2(l[0], l[1]), lp1 = __halves2half2(l[2], l[3]);
    *(uint2*)(hi + o) = make_uint2(*(uint32_t*)&hp0, *(uint32_t*)&hp1);
    *(uint2*)(lo + o) = make_uint2(*(uint32_t*)&lp0, *(uint32_t*)&lp1);
}

// -------- warp-mma GEMM: C[M,N] = A[M,K] @ B[N,K]^T, 2 fp16 products ------
#define CTA_M 128
#define CTA_N 128
#define CTA_K 64
#define NTHREADS 256
#define ARR_BYTES (128 * 128)       // 128 rows x 128B (64 halves) = 16 KB
#define STAGE_BYTES (3 * ARR_BYTES) // A, Bh, Bl = 48 KB
#define SMEM_TOTAL (2 * STAGE_BYTES)  // 96 KB -> 2 CTAs/SM

template <bool FUSE_GELU>
__global__ __launch_bounds__(NTHREADS, 2)
void gemm_wm(const __half* __restrict__ A0, const __half* __restrict__ B0,
             const __half* __restrict__ B1, float* __restrict__ Cf,
             __half* __restrict__ Ch, int M, int N, int K) {
    extern __shared__ __align__(1024) char smem[];
    uint32_t sb = smem_u32(smem);
    const int tid = threadIdx.x, warp = tid >> 5, lid = tid & 31;
    const int e = blockIdx.z;
    const int m0 = blockIdx.y * CTA_M, n0 = blockIdx.x * CTA_N;
    const int wm = (warp >> 2) * 64;    // 2 warp rows x 64
    const int wn = (warp & 3) * 32;     // 4 warp cols x 32
    const int g = lid >> 2, q = lid & 3;

    size_t eA = (size_t)e * M * K, eB = (size_t)e * N * K;
    const __half* gA = A0 + eA + (size_t)m0 * K;
    const __half* gBh = B0 + eB + (size_t)n0 * K;
    const __half* gBl = B1 + eB + (size_t)n0 * K;

    float acc[4][4][4];
#pragma unroll
    for (int mi = 0; mi < 4; mi++)
#pragma unroll
        for (int ni = 0; ni < 4; ni++)
#pragma unroll
            for (int k2 = 0; k2 < 4; k2++) acc[mi][ni][k2] = 0.0f;

    auto load_stage = [&](int kt, int s) {
        uint32_t st = sb + s * STAGE_BYTES;
        int k0 = kt * CTA_K;
#pragma unroll
        for (int i = 0; i < 4; i++) {
            int c = i * NTHREADS + tid;
            int row = c >> 3, h = c & 7;
            uint32_t rel = (uint32_t)(row * 128 + h * 16);
            uint32_t sw = SWZ(rel);
            size_t go = (size_t)row * K + k0 + h * 8;
            cp16(st + sw, gA + go);
            cp16(st + ARR_BYTES + sw, gBh + go);
            cp16(st + 2 * ARR_BYTES + sw, gBl + go);
        }
    };

    // per-warp fragment addresses (swizzled) for a given kk
    const int arow = wm + (lid & 15);
    const int brow = wn + ((lid >> 4) & 1) * 8 + (lid & 7);

    auto ldA = [&](uint32_t base, int kk, uint32_t av[4][4]) {
        uint32_t acol = (uint32_t)(kk * 2 + (lid >> 4) * 16);
#pragma unroll
        for (int mi = 0; mi < 4; mi++) {
            uint32_t ad = SWZ((uint32_t)((arow + mi * 16) * 128) + acol);
            LDSM_X4(av[mi][0], av[mi][1], av[mi][2], av[mi][3], base + ad);
        }
    };
    auto ldB = [&](uint32_t base, int kk, uint32_t bb[4][2]) {
        uint32_t bcol = (uint32_t)(kk * 2 + ((lid >> 3) & 1) * 16);
#pragma unroll
        for (int nf = 0; nf < 2; nf++) {
            uint32_t ad = SWZ((uint32_t)((brow + nf * 16) * 128) + bcol);
            LDSM_X4(bb[nf * 2][0], bb[nf * 2][1], bb[nf * 2 + 1][0], bb[nf * 2 + 1][1],
                    base + ad);
        }
    };

    // software-pipelined compute over 4 kk-steps with A/Bh double buffers
    auto compute = [&](int s) {
        uint32_t st = sb + s * STAGE_BYTES;
        uint32_t aA = st, bH = st + ARR_BYTES, bL = st + 2 * ARR_BYTES;
        uint32_t av[2][4][4], bh[2][4][2], bl[4][2];
        ldA(aA, 0, av[0]);
        ldB(bH, 0, bh[0]);
#pragma unroll
        for (int k4 = 0; k4 < 4; k4++) {
            const int cur = k4 & 1, nxt = cur ^ 1;
            ldB(bL, k4 * 16, bl);                       // Bl for current kk
            if (k4 < 3) {                               // prefetch next kk
                ldA(aA, (k4 + 1) * 16, av[nxt]);
                ldB(bH, (k4 + 1) * 16, bh[nxt]);
            }
#pragma unroll
            for (int mi = 0; mi < 4; mi++)
#pragma unroll
                for (int ni = 0; ni < 4; ni++) mma16816(acc[mi][ni], av[cur][mi], bh[cur][ni]);
#pragma unroll
            for (int mi = 0; mi < 4; mi++)
#pragma unroll
                for (int ni = 0; ni < 4; ni++) mma16816(acc[mi][ni], av[cur][mi], bl[ni]);
        }
    };

    const int NK = K / CTA_K;
    load_stage(0, 0);
    cp_commit();
    load_stage(1, 1);
    cp_commit();

    for (int kt = 0; kt < NK; kt++) {
        int s = kt & 1;
        cp_wait<1>();           // stage s loads complete
        __syncthreads();
        compute(s);
        __syncthreads();        // stage s consumed by all warps
        if (kt + 2 < NK) load_stage(kt + 2, s);
        cp_commit();            // commit every iter (possibly empty) to keep count
    }

    // ---- epilogue ----
#pragma unroll
    for (int mi = 0; mi < 4; mi++) {
#pragma unroll
        for (int ni = 0; ni < 4; ni++) {
            int r = m0 + wm + mi * 16 + g;
            int col = n0 + wn + ni * 8 + q * 2;
            size_t o0 = ((size_t)e * M + r) * N + col;
            size_t o1 = o0 + (size_t)8 * N;
            float v0 = acc[mi][ni][0], v1 = acc[mi][ni][1];
            float v2 = acc[mi][ni][2], v3 = acc[mi][ni][3];
            if (FUSE_GELU) {
                v0 = gelu_tanh_f(v0); v1 = gelu_tanh_f(v1);
                v2 = gelu_tanh_f(v2); v3 = gelu_tanh_f(v3);
                __half2 p0 = __floats2half2_rn(v0, v1);
                __half2 p1 = __floats2half2_rn(v2, v3);
                *(__half2*)(Ch + o0) = p0;
                *(__half2*)(Ch + o1) = p1;
            } else {
                *(float2*)(Cf + o0) = make_float2(v0, v1);
                *(float2*)(Cf + o1) = make_float2(v2, v3);
            }
        }
    }
}

// -------- host launch --------
extern "C" void kernel_launch(void* const* d_in, const int* in_sizes, int n_in,
                              void* d_out, int out_size) {
    const float* x = (const float*)d_in[0];
    const float* w1 = (const float*)d_in[1];
    const float* w2 = (const float*)d_in[2];
    float* out = (float*)d_out;

    __half *x16, *w1h, *w1l, *w2h, *w2l, *h16;
    cudaGetSymbolAddress((void**)&x16, g_x16);
    cudaGetSymbolAddress((void**)&w1h, g_w1h);
    cudaGetSymbolAddress((void**)&w1l, g_w1l);
    cudaGetSymbolAddress((void**)&w2h, g_w2h);
    cudaGetSymbolAddress((void**)&w2l, g_w2l);
    cudaGetSymbolAddress((void**)&h16, g_h16);

    cudaFuncSetAttribute(gemm_wm<true>, cudaFuncAttributeMaxDynamicSharedMemorySize, SMEM_TOTAL);
    cudaFuncSetAttribute(gemm_wm<false>, cudaFuncAttributeMaxDynamicSharedMemorySize, SMEM_TOTAL);

    // pre-pass
    size_t nx4 = (size_t)E_ * T_ * H_ / 4;
    conv16_k<<<(unsigned)((nx4 + 255) / 256), 256>>>(x, x16, nx4);
    tsplit16<<<dim3(F_ / 32, H_ / 32, E_), dim3(32, 8)>>>(w1, w1h, w1l, H_, F_);
    tsplit16<<<dim3(H_ / 32, F_ / 32, E_), dim3(32, 8)>>>(w2, w2h, w2l, F_, H_);

    // GEMM1 + GELU: A=x fp16 [T,H], B=w1^T fp16 hi/lo [F,H] -> h fp16 [T,F]
    gemm_wm<true><<<dim3(F_ / CTA_N, T_ / CTA_M, E_), NTHREADS, SMEM_TOTAL>>>(
        x16, w1h, w1l, nullptr, h16, T_, F_, H_);
    // GEMM2: A=h fp16 [T,F], B=w2^T fp16 hi/lo [H,F] -> out fp32 [T,H]
    gemm_wm<false><<<dim3(H_ / CTA_N, T_ / CTA_M, E_), NTHREADS, SMEM_TOTAL>>>(
        h16, w2h, w2l, out, nullptr, T_, H_, F_);
}

// round 11
// speedup vs baseline: 1.6149x; 1.5965x over previous
#include <cuda_runtime.h>
#include <cuda_bf16.h>
#include <cuda_fp16.h>
#include <cstdint>
#include <math.h>

// ============================================================================
// MLP: out[e] = gelu_tanh(x[e] @ w1[e]) @ w2[e]
//   E=8, T=2048, H=1024, F=4096, fp32 in/out.
// R11: BOTH GEMMs single-product fp16 (x, w1, h, w2 all rounded to fp16).
//   Error model (calibrated 2x): 2.08e-4 per rounding event, quadrature sum
//   -> 4 events = ~4.2e-4 (threshold 1e-3, margin 2.4x).
// warp mma.sync m16n8k16; 8 warps, warp tile 64x32, CTA 128x128x64;
// 3 stages x 32KB smem = 96KB, 2 CTAs/SM, one barrier/iter, lookahead 2.
// ============================================================================

static constexpr int E_ = 8, T_ = 2048, H_ = 1024, F_ = 4096;

// -------- static device scratch --------
__device__ __half g_x16[(size_t)E_ * T_ * H_];        // x fp16
__device__ __half g_w1t[(size_t)E_ * F_ * H_];        // w1^T: [E,F,H] fp16
__device__ __half g_w2t[(size_t)E_ * H_ * F_];        // w2^T: [E,H,F] fp16
__device__ __half g_h16[(size_t)E_ * T_ * F_];        // gelu(x@w1) fp16

// -------- helpers --------
__device__ __forceinline__ uint32_t smem_u32(const void* p) {
    return (uint32_t)__cvta_generic_to_shared(p);
}
__device__ __forceinline__ void cp16(uint32_t s, const void* g) {
    asm volatile("cp.async.cg.shared.global [%0], [%1], 16;\n"
                 :: "r"(s), "l"(__cvta_generic_to_global(g)));
}
__device__ __forceinline__ void cp_commit() {
    asm volatile("cp.async.commit_group;\n" ::: "memory");
}
template <int N> __device__ __forceinline__ void cp_wait() {
    asm volatile("cp.async.wait_group %0;\n" :: "n"(N) : "memory");
}
#define SWZ(x) ((x) ^ (((x) >> 3) & 0x70))

#define LDSM_X4(r0, r1, r2, r3, a)                                          \
    asm volatile("ldmatrix.sync.aligned.m8n8.x4.shared.b16 {%0,%1,%2,%3}, [%4];" \
                 : "=r"(r0), "=r"(r1), "=r"(r2), "=r"(r3) : "r"(a))

__device__ __forceinline__ void mma16816(float* c, const uint32_t* a, const uint32_t* b) {
    asm volatile(
        "mma.sync.aligned.m16n8k16.row.col.f32.f16.f16.f32 "
        "{%0,%1,%2,%3}, {%4,%5,%6,%7}, {%8,%9}, {%0,%1,%2,%3};\n"
        : "+f"(c[0]), "+f"(c[1]), "+f"(c[2]), "+f"(c[3])
        : "r"(a[0]), "r"(a[1]), "r"(a[2]), "r"(a[3]), "r"(b[0]), "r"(b[1]));
}

__device__ __forceinline__ float gelu_tanh_f(float x) {
    float inner = 0.7978845608028654f * (x + 0.044715f * x * x * x);
    return 0.5f * x * (1.0f + tanhf(inner));
}

// -------- pre-pass: fp32 -> fp16 convert (x) --------
__global__ void conv16_k(const float* __restrict__ in, __half* __restrict__ o, size_t n4) {
    size_t i = (size_t)blockIdx.x * blockDim.x + threadIdx.x;
    if (i >= n4) return;
    float4 v = ((const float4*)in)[i];
    __half2 a = __floats2half2_rn(v.x, v.y);
    __half2 b = __floats2half2_rn(v.z, v.w);
    ((uint2*)o)[i] = make_uint2(*(uint32_t*)&a, *(uint32_t*)&b);
}

// -------- pre-pass: transpose [E,R,C] -> [E,C,R] + fp16 convert --------
// 4 consecutive rows per thread -> 64-bit stores.
__global__ void tconv16(const float* __restrict__ in, __half* __restrict__ o,
                        int R, int C) {
    __shared__ float t[32][33];  // t[r_local][c_local]
    int e = blockIdx.z;
    const float* ip = in + (size_t)e * R * C;
    size_t ob = (size_t)e * R * C;
    int c0 = blockIdx.x * 32, r0 = blockIdx.y * 32;
    int tx = threadIdx.x, ty = threadIdx.y;
    for (int j = ty; j < 32; j += 8)
        t[j][tx] = ip[(size_t)(r0 + j) * C + c0 + tx];
    __syncthreads();
    int idx = ty * 32 + tx;          // 0..255
    int cc = idx >> 3;               // 0..31
    int rr = (idx & 7) * 4;          // 0,4,..,28
    __half2 p0 = __floats2half2_rn(t[rr][cc], t[rr + 1][cc]);
    __half2 p1 = __floats2half2_rn(t[rr + 2][cc], t[rr + 3][cc]);
    size_t off = ob + (size_t)(c0 + cc) * R + r0 + rr;
    *(uint2*)(o + off) = make_uint2(*(uint32_t*)&p0, *(uint32_t*)&p1);
}

// -------- warp-mma GEMM: C[M,N] = A[M,K] @ B[N,K]^T, single fp16 ----------
#define CTA_M 128
#define CTA_N 128
#define CTA_K 64
#define NTHREADS 256
#define ARR_BYTES (128 * 128)       // 128 rows x 128B (64 halves) = 16 KB
#define STAGE_BYTES (2 * ARR_BYTES) // A, B = 32 KB
#define NSTAGES 3
#define SMEM_TOTAL (NSTAGES * STAGE_BYTES)  // 96 KB -> 2 CTAs/SM

template <bool FUSE_GELU>
__global__ __launch_bounds__(NTHREADS, 2)
void gemm_wm(const __half* __restrict__ A0, const __half* __restrict__ B0,
             float* __restrict__ Cf, __half* __restrict__ Ch,
             int M, int N, int K) {
    extern __shared__ __align__(1024) char smem[];
    uint32_t sb = smem_u32(smem);
    const int tid = threadIdx.x, warp = tid >> 5, lid = tid & 31;
    const int e = blockIdx.z;
    const int m0 = blockIdx.y * CTA_M, n0 = blockIdx.x * CTA_N;
    const int wm = (warp >> 2) * 64;    // 2 warp rows x 64
    const int wn = (warp & 3) * 32;     // 4 warp cols x 32
    const int g = lid >> 2, q = lid & 3;

    size_t eA = (size_t)e * M * K, eB = (size_t)e * N * K;
    const __half* gA = A0 + eA + (size_t)m0 * K;
    const __half* gB = B0 + eB + (size_t)n0 * K;

    float acc[4][4][4];
#pragma unroll
    for (int mi = 0; mi < 4; mi++)
#pragma unroll
        for (int ni = 0; ni < 4; ni++)
#pragma unroll
            for (int k2 = 0; k2 < 4; k2++) acc[mi][ni][k2] = 0.0f;

    auto load_stage = [&](int kt, int s) {
        uint32_t st = sb + s * STAGE_BYTES;
        int k0 = kt * CTA_K;
#pragma unroll
        for (int i = 0; i < 4; i++) {
            int c = i * NTHREADS + tid;
            int row = c >> 3, h = c & 7;
            uint32_t rel = (uint32_t)(row * 128 + h * 16);
            uint32_t sw = SWZ(rel);
            size_t go = (size_t)row * K + k0 + h * 8;
            cp16(st + sw, gA + go);
            cp16(st + ARR_BYTES + sw, gB + go);
        }
    };

    auto compute = [&](int s) {
        uint32_t st = sb + s * STAGE_BYTES;
        uint32_t aA = st, bB = st + ARR_BYTES;
#pragma unroll
        for (int kk = 0; kk < CTA_K; kk += 16) {
            uint32_t av[4][4], bb[4][2];
            {
                int arow = wm + (lid & 15);
                uint32_t acol = (uint32_t)(kk * 2 + (lid >> 4) * 16);
#pragma unroll
                for (int mi = 0; mi < 4; mi++) {
                    uint32_t ad = SWZ((uint32_t)((arow + mi * 16) * 128) + acol);
                    LDSM_X4(av[mi][0], av[mi][1], av[mi][2], av[mi][3], aA + ad);
                }
            }
            {
                int brow = wn + ((lid >> 4) & 1) * 8 + (lid & 7);
                uint32_t bcol = (uint32_t)(kk * 2 + ((lid >> 3) & 1) * 16);
#pragma unroll
                for (int nf = 0; nf < 2; nf++) {
                    uint32_t ad = SWZ((uint32_t)((brow + nf * 16) * 128) + bcol);
                    LDSM_X4(bb[nf * 2][0], bb[nf * 2][1], bb[nf * 2 + 1][0], bb[nf * 2 + 1][1],
                            bB + ad);
                }
            }
#pragma unroll
            for (int mi = 0; mi < 4; mi++)
#pragma unroll
                for (int ni = 0; ni < 4; ni++) mma16816(acc[mi][ni], av[mi], bb[ni]);
        }
    };

    const int NK = K / CTA_K;
    load_stage(0, 0);
    cp_commit();
    load_stage(1, 1);
    cp_commit();

    for (int kt = 0; kt < NK; kt++) {
        int s = kt % NSTAGES;
        cp_wait<1>();           // stage kt loads complete (1 younger group pending)
        __syncthreads();        // data visible; next-load stage free (compute(kt-1) done)
        if (kt + 2 < NK) load_stage(kt + 2, (kt + 2) % NSTAGES);
        cp_commit();            // commit every iter (possibly empty) to keep count
        compute(s);
    }

    // ---- epilogue ----
#pragma unroll
    for (int mi = 0; mi < 4; mi++) {
#pragma unroll
        for (int ni = 0; ni < 4; ni++) {
            int r = m0 + wm + mi * 16 + g;
            int col = n0 + wn + ni * 8 + q * 2;
            size_t o0 = ((size_t)e * M + r) * N + col;
            size_t o1 = o0 + (size_t)8 * N;
            float v0 = acc[mi][ni][0], v1 = acc[mi][ni][1];
            float v2 = acc[mi][ni][2], v3 = acc[mi][ni][3];
            if (FUSE_GELU) {
                v0 = gelu_tanh_f(v0); v1 = gelu_tanh_f(v1);
                v2 = gelu_tanh_f(v2); v3 = gelu_tanh_f(v3);
                __half2 p0 = __floats2half2_rn(v0, v1);
                __half2 p1 = __floats2half2_rn(v2, v3);
                *(__half2*)(Ch + o0) = p0;
                *(__half2*)(Ch + o1) = p1;
            } else {
                *(float2*)(Cf + o0) = make_float2(v0, v1);
                *(float2*)(Cf + o1) = make_float2(v2, v3);
            }
        }
    }
}

// -------- host launch --------
extern "C" void kernel_launch(void* const* d_in, const int* in_sizes, int n_in,
                              void* d_out, int out_size) {
    const float* x = (const float*)d_in[0];
    const float* w1 = (const float*)d_in[1];
    const float* w2 = (const float*)d_in[2];
    float* out = (float*)d_out;

    __half *x16, *w1t, *w2t, *h16;
    cudaGetSymbolAddress((void**)&x16, g_x16);
    cudaGetSymbolAddress((void**)&w1t, g_w1t);
    cudaGetSymbolAddress((void**)&w2t, g_w2t);
    cudaGetSymbolAddress((void**)&h16, g_h16);

    cudaFuncSetAttribute(gemm_wm<true>, cudaFuncAttributeMaxDynamicSharedMemorySize, SMEM_TOTAL);
    cudaFuncSetAttribute(gemm_wm<false>, cudaFuncAttributeMaxDynamicSharedMemorySize, SMEM_TOTAL);

    // pre-pass
    size_t nx4 = (size_t)E_ * T_ * H_ / 4;
    conv16_k<<<(unsigned)((nx4 + 255) / 256), 256>>>(x, x16, nx4);
    tconv16<<<dim3(F_ / 32, H_ / 32, E_), dim3(32, 8)>>>(w1, w1t, H_, F_);
    tconv16<<<dim3(H_ / 32, F_ / 32, E_), dim3(32, 8)>>>(w2, w2t, F_, H_);

    // GEMM1 + GELU: A=x fp16 [T,H], B=w1^T fp16 [F,H] -> h fp16 [T,F]
    gemm_wm<true><<<dim3(F_ / CTA_N, T_ / CTA_M, E_), NTHREADS, SMEM_TOTAL>>>(
        x16, w1t, nullptr, h16, T_, F_, H_);
    // GEMM2: A=h fp16 [T,F], B=w2^T fp16 [H,F] -> out fp32 [T,H]
    gemm_wm<false><<<dim3(H_ / CTA_N, T_ / CTA_M, E_), NTHREADS, SMEM_TOTAL>>>(
        h16, w2t, out, nullptr, T_, H_, F_);
}

// round 12
// speedup vs baseline: 1.6794x; 1.0400x over previous
#include <cuda_runtime.h>
#include <cuda_bf16.h>
#include <cuda_fp16.h>
#include <cstdint>
#include <math.h>

// ============================================================================
// MLP: out[e] = gelu_tanh(x[e] @ w1[e]) @ w2[e]
//   E=8, T=2048, H=1024, F=4096, fp32 in/out.
// Both GEMMs single-product fp16 (calibrated err: 4 rounding events ~4.2e-4).
// R12: warp tile 64x64, CTA 128 threads (4 warps) x 128x128 tile, 2 CTAs/SM.
//   Fixes R11's LDS-bound regression: per kk SM-wide 256 LDS wf vs 231
//   tensor cyc (ratio 0.90) instead of 384 vs 231 (0.60).
// 3 stages x 32KB = 96KB smem, one barrier/iter, lookahead 2.
// ============================================================================

static constexpr int E_ = 8, T_ = 2048, H_ = 1024, F_ = 4096;

// -------- static device scratch --------
__device__ __half g_x16[(size_t)E_ * T_ * H_];        // x fp16
__device__ __half g_w1t[(size_t)E_ * F_ * H_];        // w1^T: [E,F,H] fp16
__device__ __half g_w2t[(size_t)E_ * H_ * F_];        // w2^T: [E,H,F] fp16
__device__ __half g_h16[(size_t)E_ * T_ * F_];        // gelu(x@w1) fp16

// -------- helpers --------
__device__ __forceinline__ uint32_t smem_u32(const void* p) {
    return (uint32_t)__cvta_generic_to_shared(p);
}
__device__ __forceinline__ void cp16(uint32_t s, const void* g) {
    asm volatile("cp.async.cg.shared.global [%0], [%1], 16;\n"
                 :: "r"(s), "l"(__cvta_generic_to_global(g)));
}
__device__ __forceinline__ void cp_commit() {
    asm volatile("cp.async.commit_group;\n" ::: "memory");
}
template <int N> __device__ __forceinline__ void cp_wait() {
    asm volatile("cp.async.wait_group %0;\n" :: "n"(N) : "memory");
}
#define SWZ(x) ((x) ^ (((x) >> 3) & 0x70))

#define LDSM_X4(r0, r1, r2, r3, a)                                          \
    asm volatile("ldmatrix.sync.aligned.m8n8.x4.shared.b16 {%0,%1,%2,%3}, [%4];" \
                 : "=r"(r0), "=r"(r1), "=r"(r2), "=r"(r3) : "r"(a))

__device__ __forceinline__ void mma16816(float* c, const uint32_t* a, const uint32_t* b) {
    asm volatile(
        "mma.sync.aligned.m16n8k16.row.col.f32.f16.f16.f32 "
        "{%0,%1,%2,%3}, {%4,%5,%6,%7}, {%8,%9}, {%0,%1,%2,%3};\n"
        : "+f"(c[0]), "+f"(c[1]), "+f"(c[2]), "+f"(c[3])
        : "r"(a[0]), "r"(a[1]), "r"(a[2]), "r"(a[3]), "r"(b[0]), "r"(b[1]));
}

__device__ __forceinline__ float gelu_tanh_f(float x) {
    float inner = 0.7978845608028654f * (x + 0.044715f * x * x * x);
    return 0.5f * x * (1.0f + tanhf(inner));
}

// -------- pre-pass: fp32 -> fp16 convert (x) --------
__global__ void conv16_k(const float* __restrict__ in, __half* __restrict__ o, size_t n4) {
    size_t i = (size_t)blockIdx.x * blockDim.x + threadIdx.x;
    if (i >= n4) return;
    float4 v = ((const float4*)in)[i];
    __half2 a = __floats2half2_rn(v.x, v.y);
    __half2 b = __floats2half2_rn(v.z, v.w);
    ((uint2*)o)[i] = make_uint2(*(uint32_t*)&a, *(uint32_t*)&b);
}

// -------- pre-pass: transpose [E,R,C] -> [E,C,R] + fp16 convert --------
__global__ void tconv16(const float* __restrict__ in, __half* __restrict__ o,
                        int R, int C) {
    __shared__ float t[32][33];  // t[r_local][c_local]
    int e = blockIdx.z;
    const float* ip = in + (size_t)e * R * C;
    size_t ob = (size_t)e * R * C;
    int c0 = blockIdx.x * 32, r0 = blockIdx.y * 32;
    int tx = threadIdx.x, ty = threadIdx.y;
    for (int j = ty; j < 32; j += 8)
        t[j][tx] = ip[(size_t)(r0 + j) * C + c0 + tx];
    __syncthreads();
    int idx = ty * 32 + tx;          // 0..255
    int cc = idx >> 3;               // 0..31
    int rr = (idx & 7) * 4;          // 0,4,..,28
    __half2 p0 = __floats2half2_rn(t[rr][cc], t[rr + 1][cc]);
    __half2 p1 = __floats2half2_rn(t[rr + 2][cc], t[rr + 3][cc]);
    size_t off = ob + (size_t)(c0 + cc) * R + r0 + rr;
    *(uint2*)(o + off) = make_uint2(*(uint32_t*)&p0, *(uint32_t*)&p1);
}

// -------- warp-mma GEMM: C[M,N] = A[M,K] @ B[N,K]^T, single fp16 ----------
#define CTA_M 128
#define CTA_N 128
#define CTA_K 64
#define NTHREADS 128
#define ARR_BYTES (128 * 128)       // 128 rows x 128B (64 halves) = 16 KB
#define STAGE_BYTES (2 * ARR_BYTES) // A, B = 32 KB
#define NSTAGES 3
#define SMEM_TOTAL (NSTAGES * STAGE_BYTES)  // 96 KB -> 2 CTAs/SM

template <bool FUSE_GELU>
__global__ __launch_bounds__(NTHREADS, 2)
void gemm_wm(const __half* __restrict__ A0, const __half* __restrict__ B0,
             float* __restrict__ Cf, __half* __restrict__ Ch,
             int M, int N, int K) {
    extern __shared__ __align__(1024) char smem[];
    uint32_t sb = smem_u32(smem);
    const int tid = threadIdx.x, warp = tid >> 5, lid = tid & 31;
    const int e = blockIdx.z;
    const int m0 = blockIdx.y * CTA_M, n0 = blockIdx.x * CTA_N;
    const int wm = (warp >> 1) * 64;    // 2 warp rows x 64
    const int wn = (warp & 1) * 64;     // 2 warp cols x 64
    const int g = lid >> 2, q = lid & 3;

    size_t eA = (size_t)e * M * K, eB = (size_t)e * N * K;
    const __half* gA = A0 + eA + (size_t)m0 * K;
    const __half* gB = B0 + eB + (size_t)n0 * K;

    float acc[4][8][4];
#pragma unroll
    for (int mi = 0; mi < 4; mi++)
#pragma unroll
        for (int ni = 0; ni < 8; ni++)
#pragma unroll
            for (int k2 = 0; k2 < 4; k2++) acc[mi][ni][k2] = 0.0f;

    auto load_stage = [&](int kt, int s) {
        uint32_t st = sb + s * STAGE_BYTES;
        int k0 = kt * CTA_K;
#pragma unroll
        for (int i = 0; i < 8; i++) {
            int c = i * NTHREADS + tid;
            int row = c >> 3, h = c & 7;
            uint32_t rel = (uint32_t)(row * 128 + h * 16);
            uint32_t sw = SWZ(rel);
            size_t go = (size_t)row * K + k0 + h * 8;
            cp16(st + sw, gA + go);
            cp16(st + ARR_BYTES + sw, gB + go);
        }
    };

    auto compute = [&](int s) {
        uint32_t st = sb + s * STAGE_BYTES;
        uint32_t aA = st, bB = st + ARR_BYTES;
#pragma unroll
        for (int kk = 0; kk < CTA_K; kk += 16) {
            uint32_t av[4][4], bb[8][2];
            {
                int arow = wm + (lid & 15);
                uint32_t acol = (uint32_t)(kk * 2 + (lid >> 4) * 16);
#pragma unroll
                for (int mi = 0; mi < 4; mi++) {
                    uint32_t ad = SWZ((uint32_t)((arow + mi * 16) * 128) + acol);
                    LDSM_X4(av[mi][0], av[mi][1], av[mi][2], av[mi][3], aA + ad);
                }
            }
            {
                int brow = wn + ((lid >> 4) & 1) * 8 + (lid & 7);
                uint32_t bcol = (uint32_t)(kk * 2 + ((lid >> 3) & 1) * 16);
#pragma unroll
                for (int nf = 0; nf < 4; nf++) {
                    uint32_t ad = SWZ((uint32_t)((brow + nf * 16) * 128) + bcol);
                    LDSM_X4(bb[nf * 2][0], bb[nf * 2][1], bb[nf * 2 + 1][0], bb[nf * 2 + 1][1],
                            bB + ad);
                }
            }
#pragma unroll
            for (int mi = 0; mi < 4; mi++)
#pragma unroll
                for (int ni = 0; ni < 8; ni++) mma16816(acc[mi][ni], av[mi], bb[ni]);
        }
    };

    const int NK = K / CTA_K;
    load_stage(0, 0);
    cp_commit();
    load_stage(1, 1);
    cp_commit();

    for (int kt = 0; kt < NK; kt++) {
        int s = kt % NSTAGES;
        cp_wait<1>();           // stage kt loads complete (1 younger group pending)
        __syncthreads();        // data visible; next-load stage free (compute(kt-1) done)
        if (kt + 2 < NK) load_stage(kt + 2, (kt + 2) % NSTAGES);
        cp_commit();            // commit every iter (possibly empty) to keep count
        compute(s);
    }

    // ---- epilogue ----
#pragma unroll
    for (int mi = 0; mi < 4; mi++) {
#pragma unroll
        for (int ni = 0; ni < 8; ni++) {
            int r = m0 + wm + mi * 16 + g;
            int col = n0 + wn + ni * 8 + q * 2;
            size_t o0 = ((size_t)e * M + r) * N + col;
            size_t o1 = o0 + (size_t)8 * N;
            float v0 = acc[mi][ni][0], v1 = acc[mi][ni][1];
            float v2 = acc[mi][ni][2], v3 = acc[mi][ni][3];
            if (FUSE_GELU) {
                v0 = gelu_tanh_f(v0); v1 = gelu_tanh_f(v1);
                v2 = gelu_tanh_f(v2); v3 = gelu_tanh_f(v3);
                __half2 p0 = __floats2half2_rn(v0, v1);
                __half2 p1 = __floats2half2_rn(v2, v3);
                *(__half2*)(Ch + o0) = p0;
                *(__half2*)(Ch + o1) = p1;
            } else {
                *(float2*)(Cf + o0) = make_float2(v0, v1);
                *(float2*)(Cf + o1) = make_float2(v2, v3);
            }
        }
    }
}

// -------- host launch --------
extern "C" void kernel_launch(void* const* d_in, const int* in_sizes, int n_in,
                              void* d_out, int out_size) {
    const float* x = (const float*)d_in[0];
    const float* w1 = (const float*)d_in[1];
    const float* w2 = (const float*)d_in[2];
    float* out = (float*)d_out;

    __half *x16, *w1t, *w2t, *h16;
    cudaGetSymbolAddress((void**)&x16, g_x16);
    cudaGetSymbolAddress((void**)&w1t, g_w1t);
    cudaGetSymbolAddress((void**)&w2t, g_w2t);
    cudaGetSymbolAddress((void**)&h16, g_h16);

    cudaFuncSetAttribute(gemm_wm<true>, cudaFuncAttributeMaxDynamicSharedMemorySize, SMEM_TOTAL);
    cudaFuncSetAttribute(gemm_wm<false>, cudaFuncAttributeMaxDynamicSharedMemorySize, SMEM_TOTAL);

    // pre-pass
    size_t nx4 = (size_t)E_ * T_ * H_ / 4;
    conv16_k<<<(unsigned)((nx4 + 255) / 256), 256>>>(x, x16, nx4);
    tconv16<<<dim3(F_ / 32, H_ / 32, E_), dim3(32, 8)>>>(w1, w1t, H_, F_);
    tconv16<<<dim3(H_ / 32, F_ / 32, E_), dim3(32, 8)>>>(w2, w2t, F_, H_);

    // GEMM1 + GELU: A=x fp16 [T,H], B=w1^T fp16 [F,H] -> h fp16 [T,F]
    gemm_wm<true><<<dim3(F_ / CTA_N, T_ / CTA_M, E_), NTHREADS, SMEM_TOTAL>>>(
        x16, w1t, nullptr, h16, T_, F_, H_);
    // GEMM2: A=h fp16 [T,F], B=w2^T fp16 [H,F] -> out fp32 [T,H]
    gemm_wm<false><<<dim3(H_ / CTA_N, T_ / CTA_M, E_), NTHREADS, SMEM_TOTAL>>>(
        h16, w2t, out, nullptr, T_, H_, F_);
}